// round 9
// baseline (speedup 1.0000x reference)
#include <cuda_runtime.h>
#include <math.h>

#define W_   512
#define H_   512
#define HW_  (512 * 512)
#define EPS  1e-8f
#define TW   56              // output columns per warp (64 loaded: [x0-4, x0+59])
#define FULLMASK 0xffffffffu

__device__ __forceinline__ float sqrt_approx(float x) {
    float r;
    asm("sqrt.approx.f32 %0, %1;" : "=f"(r) : "f"(x));
    return r;
}

__device__ __forceinline__ float smooth_l1(float a, float b) {
    float d = a - b;
    float ad = fabsf(d);
    return (ad < 1.0f) ? 0.5f * d * d : ad - 0.5f;
}

// One input row. Lane owns columns (c0, c0+1) = (x0-4+2L, x0-3+2L).
// Ring stores raw channel-reduced (v, v2) per input; vertical running sums in
// vs[]. On EMIT rows, horizontal 7-sum of the vertical sums via 6 shfls per
// array (covers both columns), then std + smooth-L1 for the 2 columns.
template <int S, bool EMIT>
__device__ __forceinline__ void rowstep(
    const float* __restrict__ P, const float* __restrict__ T,
    int gx, bool okx, bool o_ok, int oy0, int& i,
    float2 (&ring)[4][7], float2 (&vs)[4], float& acc)
{
    const int gy = oy0 - 3 + i;
    const bool ok = okx && (gy >= 0) && (gy < H_);
    const int off = (gy << 9) + gx;
    const float2 z = make_float2(0.f, 0.f);

    float2 p0 = ok ? *(const float2*)(P + off)           : z;
    float2 p1 = ok ? *(const float2*)(P + off + HW_)     : z;
    float2 p2 = ok ? *(const float2*)(P + off + 2 * HW_) : z;
    float2 t0 = ok ? *(const float2*)(T + off)           : z;
    float2 t1 = ok ? *(const float2*)(T + off + HW_)     : z;
    float2 t2 = ok ? *(const float2*)(T + off + 2 * HW_) : z;

    float2 nv[4];
    nv[0] = make_float2(p0.x + p1.x + p2.x, p0.y + p1.y + p2.y);
    nv[1] = make_float2(fmaf(p0.x, p0.x, fmaf(p1.x, p1.x, p2.x * p2.x)),
                        fmaf(p0.y, p0.y, fmaf(p1.y, p1.y, p2.y * p2.y)));
    nv[2] = make_float2(t0.x + t1.x + t2.x, t0.y + t1.y + t2.y);
    nv[3] = make_float2(fmaf(t0.x, t0.x, fmaf(t1.x, t1.x, t2.x * t2.x)),
                        fmaf(t0.y, t0.y, fmaf(t1.y, t1.y, t2.y * t2.y)));

#pragma unroll
    for (int a = 0; a < 4; a++) {
        vs[a].x += nv[a].x - ring[a][S].x;
        vs[a].y += nv[a].y - ring[a][S].y;
        ring[a][S] = nv[a];
    }

    if (EMIT) {
        float h0[4], h1[4];
#pragma unroll
        for (int a = 0; a < 4; a++) {
            float x = vs[a].x, y = vs[a].y;
            float u2y = __shfl_up_sync  (FULLMASK, y, 2);   // col c0-3
            float u1x = __shfl_up_sync  (FULLMASK, x, 1);   // col c0-2
            float u1y = __shfl_up_sync  (FULLMASK, y, 1);   // col c0-1
            float d1x = __shfl_down_sync(FULLMASK, x, 1);   // col c0+2
            float d1y = __shfl_down_sync(FULLMASK, y, 1);   // col c0+3
            float d2x = __shfl_down_sync(FULLMASK, x, 2);   // col c0+4
            h0[a] = ((u2y + u1x) + (u1y + x)) + ((y + d1x) + d1y);
            h1[a] = h0[a] - u2y + d2x;
        }
        const float inv_n = 1.0f / 147.0f;
        float mp0 = h0[0] * inv_n;
        float sp0 = sqrt_approx(fmaf(-mp0, mp0, h0[1] * inv_n) + EPS);
        float mt0 = h0[2] * inv_n;
        float st0 = sqrt_approx(fmaf(-mt0, mt0, h0[3] * inv_n) + EPS);
        float mp1 = h1[0] * inv_n;
        float sp1 = sqrt_approx(fmaf(-mp1, mp1, h1[1] * inv_n) + EPS);
        float mt1 = h1[2] * inv_n;
        float st1 = sqrt_approx(fmaf(-mt1, mt1, h1[3] * inv_n) + EPS);
        float f = smooth_l1(sp0, st0) + smooth_l1(sp1, st1);
        acc += o_ok ? f : 0.f;
    }
    i++;
}

__global__ __launch_bounds__(128)
void dist_loss_kernel(const float* __restrict__ pred,
                      const float* __restrict__ tgt,
                      float* __restrict__ out)
{
    const int L  = threadIdx.x & 31;
    const int w  = threadIdx.x >> 5;
    const int x0 = blockIdx.x * TW;
    const int oy0 = (blockIdx.y << 7) + (w << 5);     // warp's first output row
    const size_t bofs = (size_t)blockIdx.z * 3 * HW_;
    const float* P = pred + bofs;
    const float* T = tgt + bofs;

    const int gx = x0 - 4 + 2 * L;                    // even; lane's column pair
    // pairs never straddle image edges (gx even, W even)
    const bool okx = (gx >= 0) && (gx < W_);
    const bool o_ok = (L >= 2) && (L <= 29) && (gx < W_);

    float2 ring[4][7];
    float2 vs[4];
#pragma unroll
    for (int a = 0; a < 4; a++) {
        vs[a] = make_float2(0.f, 0.f);
#pragma unroll
        for (int j = 0; j < 7; j++) ring[a][j] = make_float2(0.f, 0.f);
    }

    float acc = 0.f;
    int i = 0;

    // 38 input rows: 6 warm-up (no emission), 32 emitting.
    rowstep<0, false>(P, T, gx, okx, o_ok, oy0, i, ring, vs, acc);
    rowstep<1, false>(P, T, gx, okx, o_ok, oy0, i, ring, vs, acc);
    rowstep<2, false>(P, T, gx, okx, o_ok, oy0, i, ring, vs, acc);
    rowstep<3, false>(P, T, gx, okx, o_ok, oy0, i, ring, vs, acc);
    rowstep<4, false>(P, T, gx, okx, o_ok, oy0, i, ring, vs, acc);
    rowstep<5, false>(P, T, gx, okx, o_ok, oy0, i, ring, vs, acc);
    rowstep<6, true >(P, T, gx, okx, o_ok, oy0, i, ring, vs, acc);
#pragma unroll 1
    for (int c = 0; c < 4; c++) {
        rowstep<0, true>(P, T, gx, okx, o_ok, oy0, i, ring, vs, acc);
        rowstep<1, true>(P, T, gx, okx, o_ok, oy0, i, ring, vs, acc);
        rowstep<2, true>(P, T, gx, okx, o_ok, oy0, i, ring, vs, acc);
        rowstep<3, true>(P, T, gx, okx, o_ok, oy0, i, ring, vs, acc);
        rowstep<4, true>(P, T, gx, okx, o_ok, oy0, i, ring, vs, acc);
        rowstep<5, true>(P, T, gx, okx, o_ok, oy0, i, ring, vs, acc);
        rowstep<6, true>(P, T, gx, okx, o_ok, oy0, i, ring, vs, acc);
    }
    rowstep<0, true>(P, T, gx, okx, o_ok, oy0, i, ring, vs, acc);
    rowstep<1, true>(P, T, gx, okx, o_ok, oy0, i, ring, vs, acc);
    rowstep<2, true>(P, T, gx, okx, o_ok, oy0, i, ring, vs, acc);

    // warp + block reduce
#pragma unroll
    for (int o = 16; o > 0; o >>= 1)
        acc += __shfl_xor_sync(FULLMASK, acc, o);

    __shared__ float ws[4];
    if (L == 0) ws[w] = acc;
    __syncthreads();
    if (threadIdx.x == 0) {
        float s = ws[0] + ws[1] + ws[2] + ws[3];
        atomicAdd(out, s * (1.0f / (16.0f * 512.0f * 512.0f)));
    }
}

extern "C" void kernel_launch(void* const* d_in, const int* in_sizes, int n_in,
                              void* d_out, int out_size)
{
    const float* pred = (const float*)d_in[0];
    const float* tgt  = (const float*)d_in[1];
    float* out = (float*)d_out;

    cudaMemsetAsync(out, 0, sizeof(float));

    dim3 block(128, 1, 1);
    // x: ceil(512/56) = 10, y: 512 / (32*4) = 4, z: 16  -> 640 CTAs
    dim3 grid((W_ + TW - 1) / TW, H_ / 128, 16);
    dist_loss_kernel<<<grid, block>>>(pred, tgt, out);
}

// round 10
// speedup vs baseline: 1.0991x; 1.0991x over previous
#include <cuda_runtime.h>
#include <math.h>

#define W_   512
#define H_   512
#define HW_  (512 * 512)
#define EPS  1e-8f
#define TW   26              // output columns per warp (26 + 6 halo = 32 lanes)
#define FULLMASK 0xffffffffu

__device__ __forceinline__ float sqrt_approx(float x) {
    float r;
    asm("sqrt.approx.f32 %0, %1;" : "=f"(r) : "f"(x));
    return r;
}

// h[L] = sum_{k=0..6} v[L+k] over the warp-distributed 32-vector.
// Output for lane L corresponds to column x0 + L (window center L+3).
__device__ __forceinline__ float hsum7(float v) {
    float d1 = v + __shfl_down_sync(FULLMASK, v, 1);     // 2-sum
    float d2 = d1 + __shfl_down_sync(FULLMASK, d1, 2);   // 4-sum
    float r4 = __shfl_down_sync(FULLMASK, d1, 4);        // v[c+4]+v[c+5]
    float r6 = __shfl_down_sync(FULLMASK, v, 6);         // v[c+6]
    return d2 + (r4 + r6);
}

__device__ __forceinline__ float smooth_l1(float a, float b) {
    float d = a - b;
    float ad = fabsf(d);
    return (ad < 1.0f) ? 0.5f * d * d : ad - 0.5f;
}

struct Six { float a0, a1, a2, b0, b1, b2; };

__device__ __forceinline__ Six ld6(const float* __restrict__ P,
                                   const float* __restrict__ T,
                                   int off, bool ok) {
    Six s;
    s.a0 = ok ? P[off]           : 0.f;
    s.a1 = ok ? P[off + HW_]     : 0.f;
    s.a2 = ok ? P[off + 2 * HW_] : 0.f;
    s.b0 = ok ? T[off]           : 0.f;
    s.b1 = ok ? T[off + HW_]     : 0.f;
    s.b2 = ok ? T[off + 2 * HW_] : 0.f;
    return s;
}

// One row step, vertical-first with depth-1 load pipelining.
// Consume `nxt` (row i, loaded last step), prefetch row i+1, channel-reduce,
// push raw (v, v2) per input through ring slot S into vertical sums vs[].
// On EMIT rows only: horizontal 7-sum of vs via shuffles, std, smooth-L1.
template <int S, bool EMIT>
__device__ __forceinline__ void rowstep(
    const float* __restrict__ P, const float* __restrict__ T,
    int gx, bool okx, bool out_ok, int oy0,
    int& i, Six& nxt, float (&ring)[4][7], float (&vs)[4],
    float& acc, float inv_n)
{
    Six cur = nxt;

    {   // prefetch row i+1 (last one discarded; guard predicates OOB)
        const int gy1 = oy0 - 2 + i;
        const bool ok1 = okx && (gy1 >= 0) && (gy1 < H_);
        nxt = ld6(P, T, (gy1 << 9) + gx, ok1);
    }

    float n0 = cur.a0 + cur.a1 + cur.a2;
    float n1 = fmaf(cur.a0, cur.a0, fmaf(cur.a1, cur.a1, cur.a2 * cur.a2));
    float n2 = cur.b0 + cur.b1 + cur.b2;
    float n3 = fmaf(cur.b0, cur.b0, fmaf(cur.b1, cur.b1, cur.b2 * cur.b2));

    vs[0] += n0 - ring[0][S]; ring[0][S] = n0;
    vs[1] += n1 - ring[1][S]; ring[1][S] = n1;
    vs[2] += n2 - ring[2][S]; ring[2][S] = n2;
    vs[3] += n3 - ring[3][S]; ring[3][S] = n3;

    if (EMIT) {
        float h0 = hsum7(vs[0]);
        float h1 = hsum7(vs[1]);
        float h2 = hsum7(vs[2]);
        float h3 = hsum7(vs[3]);
        float mp = h0 * inv_n;
        float sp = sqrt_approx(fmaf(-mp, mp, h1 * inv_n) + EPS);
        float mt = h2 * inv_n;
        float st = sqrt_approx(fmaf(-mt, mt, h3 * inv_n) + EPS);
        float f = smooth_l1(sp, st);
        acc += out_ok ? f : 0.f;
    }
    i++;
}

__global__ __launch_bounds__(128)
void dist_loss_kernel(const float* __restrict__ pred,
                      const float* __restrict__ tgt,
                      float* __restrict__ out)
{
    const int L  = threadIdx.x & 31;
    const int w  = threadIdx.x >> 5;
    const int x0 = blockIdx.x * TW;
    const int oy0 = (blockIdx.y << 7) + (w << 5);     // warp's first output row
    const size_t bofs = (size_t)blockIdx.z * 3 * HW_;
    const float* P = pred + bofs;
    const float* T = tgt + bofs;

    const int gx = x0 - 3 + L;                        // halo-inclusive column
    const bool okx = (gx >= 0) && (gx < W_);
    const bool out_ok = (L < TW) && ((x0 + L) < W_);

    const float inv_n = 1.0f / 147.0f;

    float ring[4][7];
    float vs[4];
#pragma unroll
    for (int a = 0; a < 4; a++) {
        vs[a] = 0.f;
#pragma unroll
        for (int j = 0; j < 7; j++) ring[a][j] = 0.f;
    }

    float acc = 0.f;
    int i = 0;

    // prime the pipeline with row 0
    Six nxt;
    {
        const int gy0 = oy0 - 3;
        const bool ok0 = okx && (gy0 >= 0);
        nxt = ld6(P, T, (gy0 << 9) + gx, ok0);
    }

    // 38 rows: 6 warm-up (slots 0..5, no emit), then 32 emitting rows
    // (slot 6, then 4 full cycles of 0..6, then 0,1,2).
    rowstep<0, false>(P, T, gx, okx, out_ok, oy0, i, nxt, ring, vs, acc, inv_n);
    rowstep<1, false>(P, T, gx, okx, out_ok, oy0, i, nxt, ring, vs, acc, inv_n);
    rowstep<2, false>(P, T, gx, okx, out_ok, oy0, i, nxt, ring, vs, acc, inv_n);
    rowstep<3, false>(P, T, gx, okx, out_ok, oy0, i, nxt, ring, vs, acc, inv_n);
    rowstep<4, false>(P, T, gx, okx, out_ok, oy0, i, nxt, ring, vs, acc, inv_n);
    rowstep<5, false>(P, T, gx, okx, out_ok, oy0, i, nxt, ring, vs, acc, inv_n);
    rowstep<6, true >(P, T, gx, okx, out_ok, oy0, i, nxt, ring, vs, acc, inv_n);
#pragma unroll 1
    for (int c = 0; c < 4; c++) {
        rowstep<0, true>(P, T, gx, okx, out_ok, oy0, i, nxt, ring, vs, acc, inv_n);
        rowstep<1, true>(P, T, gx, okx, out_ok, oy0, i, nxt, ring, vs, acc, inv_n);
        rowstep<2, true>(P, T, gx, okx, out_ok, oy0, i, nxt, ring, vs, acc, inv_n);
        rowstep<3, true>(P, T, gx, okx, out_ok, oy0, i, nxt, ring, vs, acc, inv_n);
        rowstep<4, true>(P, T, gx, okx, out_ok, oy0, i, nxt, ring, vs, acc, inv_n);
        rowstep<5, true>(P, T, gx, okx, out_ok, oy0, i, nxt, ring, vs, acc, inv_n);
        rowstep<6, true>(P, T, gx, okx, out_ok, oy0, i, nxt, ring, vs, acc, inv_n);
    }
    rowstep<0, true>(P, T, gx, okx, out_ok, oy0, i, nxt, ring, vs, acc, inv_n);
    rowstep<1, true>(P, T, gx, okx, out_ok, oy0, i, nxt, ring, vs, acc, inv_n);
    rowstep<2, true>(P, T, gx, okx, out_ok, oy0, i, nxt, ring, vs, acc, inv_n);

    // warp + block reduce
#pragma unroll
    for (int o = 16; o > 0; o >>= 1)
        acc += __shfl_xor_sync(FULLMASK, acc, o);

    __shared__ float ws[4];
    if (L == 0) ws[w] = acc;
    __syncthreads();
    if (threadIdx.x == 0) {
        float s = ws[0] + ws[1] + ws[2] + ws[3];
        atomicAdd(out, s * (1.0f / (16.0f * 512.0f * 512.0f)));
    }
}

extern "C" void kernel_launch(void* const* d_in, const int* in_sizes, int n_in,
                              void* d_out, int out_size)
{
    const float* pred = (const float*)d_in[0];
    const float* tgt  = (const float*)d_in[1];
    float* out = (float*)d_out;

    cudaMemsetAsync(out, 0, sizeof(float));

    dim3 block(128, 1, 1);
    dim3 grid((W_ + TW - 1) / TW, H_ / 128, 16);   // 20 x 4 x 16 = 1280 CTAs
    dist_loss_kernel<<<grid, block>>>(pred, tgt, out);
}